// round 1
// baseline (speedup 1.0000x reference)
#include <cuda_runtime.h>
#include <cuda_bf16.h>

#define NT 256          // threads per block
#define MAXP 1024       // max model points held in shared
#define MARGIN 0.01f

// Per-(batch, chunk) partial sums. B*S <= 2048 covered.
__device__ double g_partial[2048];

struct Rot { float r[9]; };

__device__ __forceinline__ Rot quat_rot(const float* __restrict__ q) {
    float s = q[0], u = q[1], v = q[2], w = q[3];
    Rot R;
    R.r[0] = 1.f - 2.f * (v * v + w * w);
    R.r[1] = 2.f * (u * v - s * w);
    R.r[2] = 2.f * (u * w + s * v);
    R.r[3] = 2.f * (u * v + s * w);
    R.r[4] = 1.f - 2.f * (u * u + w * w);
    R.r[5] = 2.f * (v * w - s * u);
    R.r[6] = 2.f * (u * w - s * v);
    R.r[7] = 2.f * (v * w + s * u);
    R.r[8] = 1.f - 2.f * (u * u + v * v);
    return R;
}

__global__ void add_loss_kernel(const float* __restrict__ poses_pred,
                                const float* __restrict__ poses_target,
                                const int*   __restrict__ labels,
                                const float* __restrict__ points,
                                const int*   __restrict__ symmetry,
                                int B, int C, int P, int S)
{
    const int b   = blockIdx.x;
    const int yc  = blockIdx.y;       // which P-chunk of this batch
    const int tid = threadIdx.x;
    const int slot = b * S + yc;

    __shared__ float4 sx2[MAXP];      // (x2x, x2y, x2z, ||x2||^2)
    __shared__ double sred[NT];

    const int label = labels[b];
    if (label <= 0) {                 // background: contributes 0
        if (tid == 0) g_partial[slot] = 0.0;
        return;
    }

    const float* q1 = poses_pred  + ((size_t)b * C + label) * 4;
    const float* q2 = poses_target + ((size_t)b * C + label) * 4;
    Rot R1 = quat_rot(q1);
    Rot R2 = quat_rot(q2);
    const float* mp = points + (size_t)label * P * 3;
    const bool sym = symmetry[label] > 0;

    double lsum = 0.0;
    const int p = yc * NT + tid;      // this thread's point index

    if (!sym) {
        // ADD: matched-point squared distance, only our own chunk
        if (p < P) {
            float a = mp[3 * p], bb = mp[3 * p + 1], c = mp[3 * p + 2];
            float x1x = R1.r[0] * a + R1.r[1] * bb + R1.r[2] * c;
            float x1y = R1.r[3] * a + R1.r[4] * bb + R1.r[5] * c;
            float x1z = R1.r[6] * a + R1.r[7] * bb + R1.r[8] * c;
            float x2x = R2.r[0] * a + R2.r[1] * bb + R2.r[2] * c;
            float x2y = R2.r[3] * a + R2.r[4] * bb + R2.r[5] * c;
            float x2z = R2.r[6] * a + R2.r[7] * bb + R2.r[8] * c;
            float dx = x1x - x2x, dy = x1y - x2y, dz = x1z - x2z;
            float d = dx * dx + dy * dy + dz * dz;
            lsum = (double)fmaxf(0.5f * d - MARGIN, 0.f);
        }
    } else {
        // ADD-S: fill ALL of x2 into shared (every chunk-block does the full fill;
        // it's ~15 flops/point, negligible), then min over q for our chunk's p.
        for (int j = tid; j < P && j < MAXP; j += NT) {
            float a = mp[3 * j], bb = mp[3 * j + 1], c = mp[3 * j + 2];
            float x = R2.r[0] * a + R2.r[1] * bb + R2.r[2] * c;
            float y = R2.r[3] * a + R2.r[4] * bb + R2.r[5] * c;
            float z = R2.r[6] * a + R2.r[7] * bb + R2.r[8] * c;
            sx2[j] = make_float4(x, y, z, x * x + y * y + z * z);
        }
        __syncthreads();

        float ax = 0.f, ay = 0.f, az = 0.f, n1 = 0.f;
        if (p < P) {
            float a = mp[3 * p], bb = mp[3 * p + 1], c = mp[3 * p + 2];
            float x = R1.r[0] * a + R1.r[1] * bb + R1.r[2] * c;
            float y = R1.r[3] * a + R1.r[4] * bb + R1.r[5] * c;
            float z = R1.r[6] * a + R1.r[7] * bb + R1.r[8] * c;
            ax = -2.f * x; ay = -2.f * y; az = -2.f * z;
            n1 = x * x + y * y + z * z;
        }

        // min_q ( n2[q] - 2 * x1 . x2[q] ):  1 broadcast LDS.128 + 3 FMA + 1 FMNMX / q
        float mn = 3.4028235e38f;
        #pragma unroll 8
        for (int q = 0; q < P; q++) {
            float4 s2 = sx2[q];
            float t = fmaf(ax, s2.x, fmaf(ay, s2.y, fmaf(az, s2.z, s2.w)));
            mn = fminf(mn, t);
        }

        if (p < P) {
            float d = n1 + mn;
            lsum = (double)fmaxf(0.5f * d - MARGIN, 0.f);
        }
    }

    // Deterministic block tree-reduce in double
    sred[tid] = lsum;
    __syncthreads();
    #pragma unroll
    for (int st = NT / 2; st > 0; st >>= 1) {
        if (tid < st) sred[tid] += sred[tid + st];
        __syncthreads();
    }
    if (tid == 0) g_partial[slot] = sred[0];
}

__global__ void finalize_kernel(float* __restrict__ out, int n, int B, int P)
{
    __shared__ double sred[1024];
    const int tid = threadIdx.x;
    const int nt  = blockDim.x;
    double v = 0.0;
    for (int i = tid; i < n; i += nt) v += g_partial[i];   // deterministic order
    sred[tid] = v;
    __syncthreads();
    for (int st = nt / 2; st > 0; st >>= 1) {
        if (tid < st) sred[tid] += sred[tid + st];
        __syncthreads();
    }
    if (tid == 0) out[0] = (float)(sred[0] / ((double)B * (double)P));
}

extern "C" void kernel_launch(void* const* d_in, const int* in_sizes, int n_in,
                              void* d_out, int out_size)
{
    const float* poses_pred   = (const float*)d_in[0];
    const float* poses_target = (const float*)d_in[1];
    const int*   poses_labels = (const int*)d_in[2];
    const float* points       = (const float*)d_in[3];
    const int*   symmetry     = (const int*)d_in[4];
    float* out = (float*)d_out;

    const int B = in_sizes[2];                 // labels: [B]
    const int C = in_sizes[4];                 // symmetry: [C]
    const int P = in_sizes[3] / (C * 3);       // points: [C,P,3]
    const int S = (P + NT - 1) / NT;           // P-chunks per batch

    dim3 grid(B, S);
    add_loss_kernel<<<grid, NT>>>(poses_pred, poses_target, poses_labels,
                                  points, symmetry, B, C, P, S);

    const int n = B * S;
    int bt = 1;
    while (bt < n && bt < 1024) bt <<= 1;
    finalize_kernel<<<1, bt>>>(out, n, B, P);
}

// round 3
// speedup vs baseline: 1.1042x; 1.1042x over previous
#include <cuda_runtime.h>
#include <cuda_bf16.h>

#define NT 64           // threads per block (2 warps) -> fine-grained load balance
#define MAXP 1024       // max model points held in shared
#define MARGIN 0.01f
#define FIXED_SCALE 4294967296.0   // 2^32 fixed-point for deterministic integer atomics

// Deterministic order-independent accumulator (integer atomics) + completion counter.
// Zero-initialized at module load; the last block resets them after publishing,
// so every graph replay starts from a clean state.
__device__ long long    g_acc;
__device__ unsigned int g_count;

struct Rot { float r[9]; };

__device__ __forceinline__ Rot quat_rot(const float* __restrict__ q) {
    float s = q[0], u = q[1], v = q[2], w = q[3];
    Rot R;
    R.r[0] = 1.f - 2.f * (v * v + w * w);
    R.r[1] = 2.f * (u * v - s * w);
    R.r[2] = 2.f * (u * w + s * v);
    R.r[3] = 2.f * (u * v + s * w);
    R.r[4] = 1.f - 2.f * (u * u + w * w);
    R.r[5] = 2.f * (v * w - s * u);
    R.r[6] = 2.f * (u * w - s * v);
    R.r[7] = 2.f * (v * w + s * u);
    R.r[8] = 1.f - 2.f * (u * u + v * v);
    return R;
}

__global__ void add_loss_kernel(const float* __restrict__ poses_pred,
                                const float* __restrict__ poses_target,
                                const int*   __restrict__ labels,
                                const float* __restrict__ points,
                                const int*   __restrict__ symmetry,
                                float* __restrict__ out,
                                int B, int C, int P, int S)
{
    const int b   = blockIdx.x;
    const int yc  = blockIdx.y;       // which P-chunk of this batch
    const int tid = threadIdx.x;
    const unsigned int total_blocks = gridDim.x * gridDim.y;

    __shared__ float4 sx2[MAXP];      // (x2x, x2y, x2z, ||x2||^2)
    __shared__ double swarp[NT / 32];

    const int label = labels[b];
    double lsum = 0.0;

    if (label > 0) {
        const float* q1 = poses_pred   + ((size_t)b * C + label) * 4;
        const float* q2 = poses_target + ((size_t)b * C + label) * 4;
        Rot R1 = quat_rot(q1);
        Rot R2 = quat_rot(q2);
        const float* mp = points + (size_t)label * P * 3;
        const bool sym = symmetry[label] > 0;

        const int p = yc * NT + tid;  // this thread's point index

        if (!sym) {
            // ADD: matched-point squared distance, own chunk only.
            // Same formulation as the reference: rotate separately, then subtract.
            if (p < P) {
                float a = mp[3 * p], bb = mp[3 * p + 1], c = mp[3 * p + 2];
                float x1x = R1.r[0] * a + R1.r[1] * bb + R1.r[2] * c;
                float x1y = R1.r[3] * a + R1.r[4] * bb + R1.r[5] * c;
                float x1z = R1.r[6] * a + R1.r[7] * bb + R1.r[8] * c;
                float x2x = R2.r[0] * a + R2.r[1] * bb + R2.r[2] * c;
                float x2y = R2.r[3] * a + R2.r[4] * bb + R2.r[5] * c;
                float x2z = R2.r[6] * a + R2.r[7] * bb + R2.r[8] * c;
                float dx = x1x - x2x, dy = x1y - x2y, dz = x1z - x2z;
                float d = dx * dx + dy * dy + dz * dz;
                lsum = (double)fmaxf(0.5f * d - MARGIN, 0.f);
            }
        } else {
            // ADD-S: every chunk-block fills the full x2 tile (cheap, ~15 flops/pt),
            // then computes min over all q for its own chunk of p.
            for (int j = tid; j < P && j < MAXP; j += NT) {
                float a = mp[3 * j], bb = mp[3 * j + 1], c = mp[3 * j + 2];
                float x = R2.r[0] * a + R2.r[1] * bb + R2.r[2] * c;
                float y = R2.r[3] * a + R2.r[4] * bb + R2.r[5] * c;
                float z = R2.r[6] * a + R2.r[7] * bb + R2.r[8] * c;
                sx2[j] = make_float4(x, y, z, x * x + y * y + z * z);
            }
            __syncthreads();

            float ax = 0.f, ay = 0.f, az = 0.f, n1 = 0.f;
            if (p < P) {
                float a = mp[3 * p], bb = mp[3 * p + 1], c = mp[3 * p + 2];
                float x = R1.r[0] * a + R1.r[1] * bb + R1.r[2] * c;
                float y = R1.r[3] * a + R1.r[4] * bb + R1.r[5] * c;
                float z = R1.r[6] * a + R1.r[7] * bb + R1.r[8] * c;
                ax = -2.f * x; ay = -2.f * y; az = -2.f * z;
                n1 = x * x + y * y + z * z;
            }

            // min_q ( n2[q] - 2 * x1 . x2[q] ) with 4 independent accumulators
            // to break the FMNMX dependency chain (4cyc/iter -> ~1cyc/iter).
            const float INF = 3.4028235e38f;
            float mn0 = INF, mn1 = INF, mn2 = INF, mn3 = INF;
            #pragma unroll 4
            for (int q = 0; q < P; q += 4) {
                float4 s0 = sx2[q];
                float4 s1 = sx2[q + 1];
                float4 s2 = sx2[q + 2];
                float4 s3 = sx2[q + 3];
                float t0 = fmaf(ax, s0.x, fmaf(ay, s0.y, fmaf(az, s0.z, s0.w)));
                float t1 = fmaf(ax, s1.x, fmaf(ay, s1.y, fmaf(az, s1.z, s1.w)));
                float t2 = fmaf(ax, s2.x, fmaf(ay, s2.y, fmaf(az, s2.z, s2.w)));
                float t3 = fmaf(ax, s3.x, fmaf(ay, s3.y, fmaf(az, s3.z, s3.w)));
                mn0 = fminf(mn0, t0);
                mn1 = fminf(mn1, t1);
                mn2 = fminf(mn2, t2);
                mn3 = fminf(mn3, t3);
            }
            float mn = fminf(fminf(mn0, mn1), fminf(mn2, mn3));

            if (p < P) {
                float d = n1 + mn;
                lsum = (double)fmaxf(0.5f * d - MARGIN, 0.f);
            }
        }
    }

    // ---- block reduction (warp shuffle in double, then across 2 warps) ----
    const int lane = tid & 31;
    const int wid  = tid >> 5;
    #pragma unroll
    for (int off = 16; off > 0; off >>= 1)
        lsum += __shfl_down_sync(0xFFFFFFFFu, lsum, off);
    if (lane == 0) swarp[wid] = lsum;
    __syncthreads();

    if (tid == 0) {
        double bsum = 0.0;
        #pragma unroll
        for (int w = 0; w < NT / 32; w++) bsum += swarp[w];

        // Deterministic fixed-point accumulate (integer add is order-independent)
        long long contrib = (long long)llrint(bsum * FIXED_SCALE);
        if (contrib != 0) atomicAdd((unsigned long long*)&g_acc, (unsigned long long)contrib);
        __threadfence();

        unsigned int prev = atomicAdd(&g_count, 1u);
        if (prev == total_blocks - 1) {
            // last block: publish result and reset state for the next graph replay
            long long acc = (long long)atomicAdd((unsigned long long*)&g_acc, 0ull);
            out[0] = (float)(((double)acc / FIXED_SCALE) / ((double)B * (double)P));
            g_acc = 0;
            g_count = 0;
            __threadfence();
        }
    }
}

extern "C" void kernel_launch(void* const* d_in, const int* in_sizes, int n_in,
                              void* d_out, int out_size)
{
    const float* poses_pred   = (const float*)d_in[0];
    const float* poses_target = (const float*)d_in[1];
    const int*   poses_labels = (const int*)d_in[2];
    const float* points       = (const float*)d_in[3];
    const int*   symmetry     = (const int*)d_in[4];
    float* out = (float*)d_out;

    const int B = in_sizes[2];                 // labels: [B]
    const int C = in_sizes[4];                 // symmetry: [C]
    const int P = in_sizes[3] / (C * 3);       // points: [C,P,3]
    const int S = (P + NT - 1) / NT;           // P-chunks per batch

    dim3 grid(B, S);
    add_loss_kernel<<<grid, NT>>>(poses_pred, poses_target, poses_labels,
                                  points, symmetry, out, B, C, P, S);
}

// round 4
// speedup vs baseline: 1.3668x; 1.2378x over previous
#include <cuda_runtime.h>
#include <cuda_bf16.h>

#define NT 32               // 1 warp per block -> finest load-balance grain
#define PPT 2               // points per thread
#define PTS_PER_BLK (NT * PPT)   // 64
#define MAXPAIR 512         // max q-pairs in shared (P<=1024)
#define MARGIN 0.01f
#define FIXED_SCALE 4294967296.0

// Deterministic order-independent accumulator + completion counter.
// Last block publishes and resets, so graph replays start clean.
__device__ long long    g_acc;
__device__ unsigned int g_count;

struct Rot { float r[9]; };

__device__ __forceinline__ Rot quat_rot(const float* __restrict__ q) {
    float s = q[0], u = q[1], v = q[2], w = q[3];
    Rot R;
    R.r[0] = 1.f - 2.f * (v * v + w * w);
    R.r[1] = 2.f * (u * v - s * w);
    R.r[2] = 2.f * (u * w + s * v);
    R.r[3] = 2.f * (u * v + s * w);
    R.r[4] = 1.f - 2.f * (u * u + w * w);
    R.r[5] = 2.f * (v * w - s * u);
    R.r[6] = 2.f * (u * w - s * v);
    R.r[7] = 2.f * (v * w + s * u);
    R.r[8] = 1.f - 2.f * (u * u + v * v);
    return R;
}

// ---- packed f32x2 helpers (Blackwell FFMA2: 2 fp32 MACs / instruction) ----
__device__ __forceinline__ double ffma2(double a, double b, double c) {
    double d;
    asm("fma.rn.f32x2 %0, %1, %2, %3;"
        : "=d"(d) : "d"(a), "d"(b), "d"(c));
    return d;
}
__device__ __forceinline__ double splat2(float x) {
    double d;
    asm("mov.b64 %0, {%1, %1};" : "=d"(d) : "f"(x));
    return d;
}
__device__ __forceinline__ float lo32(double d) {
    return __int_as_float(__double2loint(d));
}
__device__ __forceinline__ float hi32(double d) {
    return __int_as_float(__double2hiint(d));
}

__global__ void __launch_bounds__(NT)
add_loss_kernel(const float* __restrict__ poses_pred,
                const float* __restrict__ poses_target,
                const int*   __restrict__ labels,
                const float* __restrict__ points,
                const int*   __restrict__ symmetry,
                float* __restrict__ out,
                int B, int C, int P, int S)
{
    const int b   = blockIdx.x;
    const int yc  = blockIdx.y;
    const int tid = threadIdx.x;
    const unsigned int total_blocks = gridDim.x * gridDim.y;

    // q-pair tile: sA[j]=(x_2j, x_2j+1, y_2j, y_2j+1), sB[j]=(z.., w..) where w=||x2||^2
    __shared__ float4 sA[MAXPAIR];
    __shared__ float4 sB[MAXPAIR];

    const int label = labels[b];
    double lsum = 0.0;

    if (label > 0) {
        const float* q1 = poses_pred   + ((size_t)b * C + label) * 4;
        const float* q2 = poses_target + ((size_t)b * C + label) * 4;
        Rot R1 = quat_rot(q1);
        Rot R2 = quat_rot(q2);
        const float* mp = points + (size_t)label * P * 3;
        const bool sym = symmetry[label] > 0;

        const int p0 = yc * PTS_PER_BLK + tid;        // first point
        const int p1 = p0 + NT;                       // second point

        if (!sym) {
            // ADD: matched-point distance, reference formulation
            #pragma unroll
            for (int k = 0; k < PPT; k++) {
                int p = p0 + k * NT;
                if (p < P) {
                    float a = mp[3 * p], bb = mp[3 * p + 1], c = mp[3 * p + 2];
                    float x1x = R1.r[0]*a + R1.r[1]*bb + R1.r[2]*c;
                    float x1y = R1.r[3]*a + R1.r[4]*bb + R1.r[5]*c;
                    float x1z = R1.r[6]*a + R1.r[7]*bb + R1.r[8]*c;
                    float x2x = R2.r[0]*a + R2.r[1]*bb + R2.r[2]*c;
                    float x2y = R2.r[3]*a + R2.r[4]*bb + R2.r[5]*c;
                    float x2z = R2.r[6]*a + R2.r[7]*bb + R2.r[8]*c;
                    float dx = x1x - x2x, dy = x1y - x2y, dz = x1z - x2z;
                    float d = dx*dx + dy*dy + dz*dz;
                    lsum += (double)fmaxf(0.5f * d - MARGIN, 0.f);
                }
            }
        } else {
            const int npairs = P >> 1;
            // fill full x2 tile as q-pairs (redundant per chunk-block; cheap)
            for (int j = tid; j < npairs; j += NT) {
                int qa = 2 * j, qb = 2 * j + 1;
                float a0 = mp[3*qa], b0 = mp[3*qa+1], c0 = mp[3*qa+2];
                float a1 = mp[3*qb], b1 = mp[3*qb+1], c1 = mp[3*qb+2];
                float x0 = R2.r[0]*a0 + R2.r[1]*b0 + R2.r[2]*c0;
                float y0 = R2.r[3]*a0 + R2.r[4]*b0 + R2.r[5]*c0;
                float z0 = R2.r[6]*a0 + R2.r[7]*b0 + R2.r[8]*c0;
                float x1 = R2.r[0]*a1 + R2.r[1]*b1 + R2.r[2]*c1;
                float y1 = R2.r[3]*a1 + R2.r[4]*b1 + R2.r[5]*c1;
                float z1 = R2.r[6]*a1 + R2.r[7]*b1 + R2.r[8]*c1;
                sA[j] = make_float4(x0, x1, y0, y1);
                sB[j] = make_float4(z0, z1,
                                    x0*x0 + y0*y0 + z0*z0,
                                    x1*x1 + y1*y1 + z1*z1);
            }
            __syncthreads();

            // per-thread point data: splat -2*x1 into f32x2 pairs
            float n1a = 0.f, n1b = 0.f;
            double A0x = 0, A0y = 0, A0z = 0, A1x = 0, A1y = 0, A1z = 0;
            if (p0 < P) {
                float a = mp[3*p0], bb = mp[3*p0+1], c = mp[3*p0+2];
                float x = R1.r[0]*a + R1.r[1]*bb + R1.r[2]*c;
                float y = R1.r[3]*a + R1.r[4]*bb + R1.r[5]*c;
                float z = R1.r[6]*a + R1.r[7]*bb + R1.r[8]*c;
                A0x = splat2(-2.f*x); A0y = splat2(-2.f*y); A0z = splat2(-2.f*z);
                n1a = x*x + y*y + z*z;
            }
            if (p1 < P) {
                float a = mp[3*p1], bb = mp[3*p1+1], c = mp[3*p1+2];
                float x = R1.r[0]*a + R1.r[1]*bb + R1.r[2]*c;
                float y = R1.r[3]*a + R1.r[4]*bb + R1.r[5]*c;
                float z = R1.r[6]*a + R1.r[7]*bb + R1.r[8]*c;
                A1x = splat2(-2.f*x); A1y = splat2(-2.f*y); A1z = splat2(-2.f*z);
                n1b = x*x + y*y + z*z;
            }

            // min over q: packed 2-q FFMA2, 4 independent min accumulators
            const float INF = 3.4028235e38f;
            float m00 = INF, m01 = INF, m10 = INF, m11 = INF;
            const double2* __restrict__ pA = (const double2*)sA;  // (x01, y01)
            const double2* __restrict__ pB = (const double2*)sB;  // (z01, w01)
            #pragma unroll 4
            for (int j = 0; j < npairs; j++) {
                double2 v1 = pA[j];
                double2 v2 = pB[j];
                double t0 = ffma2(A0x, v1.x, ffma2(A0y, v1.y, ffma2(A0z, v2.x, v2.y)));
                double t1 = ffma2(A1x, v1.x, ffma2(A1y, v1.y, ffma2(A1z, v2.x, v2.y)));
                m00 = fminf(m00, lo32(t0));
                m01 = fminf(m01, hi32(t0));
                m10 = fminf(m10, lo32(t1));
                m11 = fminf(m11, hi32(t1));
            }
            float mn0 = fminf(m00, m01);
            float mn1 = fminf(m10, m11);

            if (p0 < P) lsum += (double)fmaxf(0.5f * (n1a + mn0) - MARGIN, 0.f);
            if (p1 < P) lsum += (double)fmaxf(0.5f * (n1b + mn1) - MARGIN, 0.f);
        }
    }

    // ---- warp reduction (single warp per block) ----
    #pragma unroll
    for (int off = 16; off > 0; off >>= 1)
        lsum += __shfl_down_sync(0xFFFFFFFFu, lsum, off);

    if (tid == 0) {
        long long contrib = (long long)llrint(lsum * FIXED_SCALE);
        if (contrib != 0) atomicAdd((unsigned long long*)&g_acc, (unsigned long long)contrib);
        __threadfence();

        unsigned int prev = atomicAdd(&g_count, 1u);
        if (prev == total_blocks - 1) {
            long long acc = (long long)atomicAdd((unsigned long long*)&g_acc, 0ull);
            out[0] = (float)(((double)acc / FIXED_SCALE) / ((double)B * (double)P));
            g_acc = 0;
            g_count = 0;
            __threadfence();
        }
    }
}

extern "C" void kernel_launch(void* const* d_in, const int* in_sizes, int n_in,
                              void* d_out, int out_size)
{
    const float* poses_pred   = (const float*)d_in[0];
    const float* poses_target = (const float*)d_in[1];
    const int*   poses_labels = (const int*)d_in[2];
    const float* points       = (const float*)d_in[3];
    const int*   symmetry     = (const int*)d_in[4];
    float* out = (float*)d_out;

    const int B = in_sizes[2];                 // labels: [B]
    const int C = in_sizes[4];                 // symmetry: [C]
    const int P = in_sizes[3] / (C * 3);       // points: [C,P,3]
    const int S = (P + PTS_PER_BLK - 1) / PTS_PER_BLK;

    dim3 grid(B, S);
    add_loss_kernel<<<grid, NT>>>(poses_pred, poses_target, poses_labels,
                                  points, symmetry, out, B, C, P, S);
}

// round 5
// speedup vs baseline: 1.4662x; 1.0727x over previous
#include <cuda_runtime.h>
#include <cuda_bf16.h>

#define NT 64               // 2 warps per block: share the smem tile -> 2x residency
#define PPT 2               // points per thread
#define PTS_PER_BLK (NT * PPT)   // 128
#define MAXPAIR 512         // max q-pairs in shared (P<=1024)
#define MARGIN 0.01f
#define FIXED_SCALE 4294967296.0

// Deterministic order-independent accumulator + completion counter.
// Last block publishes and resets, so graph replays start clean.
__device__ long long    g_acc;
__device__ unsigned int g_count;

struct Rot { float r[9]; };

__device__ __forceinline__ Rot quat_rot(const float* __restrict__ q) {
    float s = q[0], u = q[1], v = q[2], w = q[3];
    Rot R;
    R.r[0] = 1.f - 2.f * (v * v + w * w);
    R.r[1] = 2.f * (u * v - s * w);
    R.r[2] = 2.f * (u * w + s * v);
    R.r[3] = 2.f * (u * v + s * w);
    R.r[4] = 1.f - 2.f * (u * u + w * w);
    R.r[5] = 2.f * (v * w - s * u);
    R.r[6] = 2.f * (u * w - s * v);
    R.r[7] = 2.f * (v * w + s * u);
    R.r[8] = 1.f - 2.f * (u * u + v * v);
    return R;
}

// ---- packed f32x2 helpers (Blackwell FFMA2: 2 fp32 MACs / instruction) ----
__device__ __forceinline__ double ffma2(double a, double b, double c) {
    double d;
    asm("fma.rn.f32x2 %0, %1, %2, %3;"
        : "=d"(d) : "d"(a), "d"(b), "d"(c));
    return d;
}
__device__ __forceinline__ double splat2(float x) {
    double d;
    asm("mov.b64 %0, {%1, %1};" : "=d"(d) : "f"(x));
    return d;
}
__device__ __forceinline__ float lo32(double d) {
    return __int_as_float(__double2loint(d));
}
__device__ __forceinline__ float hi32(double d) {
    return __int_as_float(__double2hiint(d));
}

__global__ void __launch_bounds__(NT)
add_loss_kernel(const float* __restrict__ poses_pred,
                const float* __restrict__ poses_target,
                const int*   __restrict__ labels,
                const float* __restrict__ points,
                const int*   __restrict__ symmetry,
                float* __restrict__ out,
                int B, int C, int P, int S)
{
    const int b   = blockIdx.x;
    const int yc  = blockIdx.y;
    const int tid = threadIdx.x;
    const unsigned int total_blocks = gridDim.x * gridDim.y;

    // q-pair tile: sA[j]=(x_2j, x_2j+1, y_2j, y_2j+1), sB[j]=(z0,z1,||x2_0||^2,||x2_1||^2)
    __shared__ float4 sA[MAXPAIR];
    __shared__ float4 sB[MAXPAIR];
    __shared__ double swarp[NT / 32];

    const int label = labels[b];
    double lsum = 0.0;

    if (label > 0) {
        const float* q1 = poses_pred   + ((size_t)b * C + label) * 4;
        const float* q2 = poses_target + ((size_t)b * C + label) * 4;
        Rot R1 = quat_rot(q1);
        Rot R2 = quat_rot(q2);
        const float* mp = points + (size_t)label * P * 3;
        const bool sym = symmetry[label] > 0;

        const int p0 = yc * PTS_PER_BLK + tid;        // first point
        const int p1 = p0 + NT;                       // second point

        if (!sym) {
            // ADD: matched-point distance, reference formulation
            #pragma unroll
            for (int k = 0; k < PPT; k++) {
                int p = p0 + k * NT;
                if (p < P) {
                    float a = mp[3 * p], bb = mp[3 * p + 1], c = mp[3 * p + 2];
                    float x1x = R1.r[0]*a + R1.r[1]*bb + R1.r[2]*c;
                    float x1y = R1.r[3]*a + R1.r[4]*bb + R1.r[5]*c;
                    float x1z = R1.r[6]*a + R1.r[7]*bb + R1.r[8]*c;
                    float x2x = R2.r[0]*a + R2.r[1]*bb + R2.r[2]*c;
                    float x2y = R2.r[3]*a + R2.r[4]*bb + R2.r[5]*c;
                    float x2z = R2.r[6]*a + R2.r[7]*bb + R2.r[8]*c;
                    float dx = x1x - x2x, dy = x1y - x2y, dz = x1z - x2z;
                    float d = dx*dx + dy*dy + dz*dz;
                    lsum += (double)fmaxf(0.5f * d - MARGIN, 0.f);
                }
            }
        } else {
            const int npairs = P >> 1;
            // fill full x2 tile as q-pairs (shared by both warps; 8 iters/thread)
            for (int j = tid; j < npairs; j += NT) {
                int qa = 2 * j, qb = 2 * j + 1;
                float a0 = mp[3*qa], b0 = mp[3*qa+1], c0 = mp[3*qa+2];
                float a1 = mp[3*qb], b1 = mp[3*qb+1], c1 = mp[3*qb+2];
                float x0 = R2.r[0]*a0 + R2.r[1]*b0 + R2.r[2]*c0;
                float y0 = R2.r[3]*a0 + R2.r[4]*b0 + R2.r[5]*c0;
                float z0 = R2.r[6]*a0 + R2.r[7]*b0 + R2.r[8]*c0;
                float x1 = R2.r[0]*a1 + R2.r[1]*b1 + R2.r[2]*c1;
                float y1 = R2.r[3]*a1 + R2.r[4]*b1 + R2.r[5]*c1;
                float z1 = R2.r[6]*a1 + R2.r[7]*b1 + R2.r[8]*c1;
                sA[j] = make_float4(x0, x1, y0, y1);
                sB[j] = make_float4(z0, z1,
                                    x0*x0 + y0*y0 + z0*z0,
                                    x1*x1 + y1*y1 + z1*z1);
            }
            __syncthreads();

            // per-thread point data: splat -2*x1 into f32x2 pairs
            float n1a = 0.f, n1b = 0.f;
            double A0x = 0, A0y = 0, A0z = 0, A1x = 0, A1y = 0, A1z = 0;
            if (p0 < P) {
                float a = mp[3*p0], bb = mp[3*p0+1], c = mp[3*p0+2];
                float x = R1.r[0]*a + R1.r[1]*bb + R1.r[2]*c;
                float y = R1.r[3]*a + R1.r[4]*bb + R1.r[5]*c;
                float z = R1.r[6]*a + R1.r[7]*bb + R1.r[8]*c;
                A0x = splat2(-2.f*x); A0y = splat2(-2.f*y); A0z = splat2(-2.f*z);
                n1a = x*x + y*y + z*z;
            }
            if (p1 < P) {
                float a = mp[3*p1], bb = mp[3*p1+1], c = mp[3*p1+2];
                float x = R1.r[0]*a + R1.r[1]*bb + R1.r[2]*c;
                float y = R1.r[3]*a + R1.r[4]*bb + R1.r[5]*c;
                float z = R1.r[6]*a + R1.r[7]*bb + R1.r[8]*c;
                A1x = splat2(-2.f*x); A1y = splat2(-2.f*y); A1z = splat2(-2.f*z);
                n1b = x*x + y*y + z*z;
            }

            // min over q: packed 2-q FFMA2, 4 independent min accumulators
            const float INF = 3.4028235e38f;
            float m00 = INF, m01 = INF, m10 = INF, m11 = INF;
            const double2* __restrict__ pA = (const double2*)sA;  // (x01, y01)
            const double2* __restrict__ pB = (const double2*)sB;  // (z01, w01)
            #pragma unroll 4
            for (int j = 0; j < npairs; j++) {
                double2 v1 = pA[j];
                double2 v2 = pB[j];
                double t0 = ffma2(A0x, v1.x, ffma2(A0y, v1.y, ffma2(A0z, v2.x, v2.y)));
                double t1 = ffma2(A1x, v1.x, ffma2(A1y, v1.y, ffma2(A1z, v2.x, v2.y)));
                m00 = fminf(m00, lo32(t0));
                m01 = fminf(m01, hi32(t0));
                m10 = fminf(m10, lo32(t1));
                m11 = fminf(m11, hi32(t1));
            }
            float mn0 = fminf(m00, m01);
            float mn1 = fminf(m10, m11);

            if (p0 < P) lsum += (double)fmaxf(0.5f * (n1a + mn0) - MARGIN, 0.f);
            if (p1 < P) lsum += (double)fmaxf(0.5f * (n1b + mn1) - MARGIN, 0.f);
        }
    }

    // ---- block reduction: warp shuffle, then across 2 warps ----
    const int lane = tid & 31;
    const int wid  = tid >> 5;
    #pragma unroll
    for (int off = 16; off > 0; off >>= 1)
        lsum += __shfl_down_sync(0xFFFFFFFFu, lsum, off);
    if (lane == 0) swarp[wid] = lsum;
    __syncthreads();

    if (tid == 0) {
        double bsum = swarp[0] + swarp[1];

        long long contrib = (long long)llrint(bsum * FIXED_SCALE);
        if (contrib != 0) atomicAdd((unsigned long long*)&g_acc, (unsigned long long)contrib);
        __threadfence();

        unsigned int prev = atomicAdd(&g_count, 1u);
        if (prev == total_blocks - 1) {
            long long acc = (long long)atomicAdd((unsigned long long*)&g_acc, 0ull);
            out[0] = (float)(((double)acc / FIXED_SCALE) / ((double)B * (double)P));
            g_acc = 0;
            g_count = 0;
            __threadfence();
        }
    }
}

extern "C" void kernel_launch(void* const* d_in, const int* in_sizes, int n_in,
                              void* d_out, int out_size)
{
    const float* poses_pred   = (const float*)d_in[0];
    const float* poses_target = (const float*)d_in[1];
    const int*   poses_labels = (const int*)d_in[2];
    const float* points       = (const float*)d_in[3];
    const int*   symmetry     = (const int*)d_in[4];
    float* out = (float*)d_out;

    const int B = in_sizes[2];                 // labels: [B]
    const int C = in_sizes[4];                 // symmetry: [C]
    const int P = in_sizes[3] / (C * 3);       // points: [C,P,3]
    const int S = (P + PTS_PER_BLK - 1) / PTS_PER_BLK;

    dim3 grid(B, S);
    add_loss_kernel<<<grid, NT>>>(poses_pred, poses_target, poses_labels,
                                  points, symmetry, out, B, C, P, S);
}